// round 11
// baseline (speedup 1.0000x reference)
#include <cuda_runtime.h>
#include <cuda_bf16.h>
#include <cstdint>

// ============================================================================
// Problem constants
// ============================================================================
#define BATCH   4096
#define DIM     256
#define NROWS   8192          // 2*BATCH
#define INV_TAU 2.0f          // 1/0.5

// GEMM tiling: 128x128 output tile, K chunked by 64, upper-tri tiles only
// 4 warps per CTA, each owning a 64x64 warptile (2x2 warp grid)
#define MT      128
#define NT      128
#define NTILE   64            // 64x64 tile grid; jt >= it: 2080 CTAs
#define N_CTAS  (NTILE * (NTILE + 1) / 2)
#define NSTAGE  3

// ============================================================================
// Device-global scratch
// ============================================================================
__device__ __align__(16) __nv_bfloat16 g_zn[NROWS * DIM];  // normalized, bf16
__device__ float g_rowsum[NROWS];
__device__ float g_pos[BATCH];                             // S[i, i+BATCH]

// ============================================================================
// Helpers
// ============================================================================
__device__ __forceinline__ uint32_t smem_to_u32(const void* smem_ptr) {
    uint32_t addr;
    asm("{ .reg .u64 tmp; cvta.to.shared.u64 tmp, %1; cvt.u32.u64 %0, tmp; }"
        : "=r"(addr) : "l"(smem_ptr));
    return addr;
}

__device__ __forceinline__ void cp_async16(uint32_t smem_addr, const void* gptr) {
    asm volatile("cp.async.cg.shared.global [%0], [%1], 16;"
                 :: "r"(smem_addr), "l"(gptr) : "memory");
}
__device__ __forceinline__ void cp_async_commit() {
    asm volatile("cp.async.commit_group;" ::: "memory");
}
template <int N>
__device__ __forceinline__ void cp_async_wait() {
    asm volatile("cp.async.wait_group %0;" :: "n"(N) : "memory");
}

__device__ __forceinline__ void ldmatrix_x4(uint32_t& r0, uint32_t& r1,
                                            uint32_t& r2, uint32_t& r3,
                                            uint32_t addr) {
    asm volatile("ldmatrix.sync.aligned.m8n8.x4.shared.b16 {%0,%1,%2,%3}, [%4];"
                 : "=r"(r0), "=r"(r1), "=r"(r2), "=r"(r3) : "r"(addr));
}

// mma.sync m16n8k16 bf16 -> f32, row-major A, col-major B
__device__ __forceinline__ void mma16816(float* c,
                                         uint32_t a0, uint32_t a1, uint32_t a2, uint32_t a3,
                                         uint32_t b0, uint32_t b1) {
    asm volatile(
        "mma.sync.aligned.m16n8k16.row.col.f32.bf16.bf16.f32 "
        "{%0,%1,%2,%3}, {%4,%5,%6,%7}, {%8,%9}, {%0,%1,%2,%3};"
        : "+f"(c[0]), "+f"(c[1]), "+f"(c[2]), "+f"(c[3])
        : "r"(a0), "r"(a1), "r"(a2), "r"(a3), "r"(b0), "r"(b1));
}

// SW128-style swizzle for 128-byte rows
#define SWZ(off) ((off) ^ (((off) >> 3) & 0x70))

// ============================================================================
// SMEM layout (dynamic): NSTAGE stages of {A:128x128B, B:128x128B}
// ============================================================================
static constexpr int STAGE_A    = 0;
static constexpr int STAGE_B    = 16384;
static constexpr int STAGE_SZ   = 32768;
static constexpr int SMEM_R_OFF = NSTAGE * STAGE_SZ;            // 98304
static constexpr int SMEM_C_OFF = SMEM_R_OFF + 128 * 4;
static constexpr int SMEM_TOTAL = SMEM_C_OFF + 128 * 4;         // 99328

// ============================================================================
// Kernel 1: L2-normalize rows -> bf16 (also zero-inits g_rowsum)
// ============================================================================
__global__ void __launch_bounds__(256) normalize_kernel(
    const float* __restrict__ z_orig,
    const float* __restrict__ z_aug
) {
    int wid = threadIdx.x >> 5;
    int lid = threadIdx.x & 31;
    int row = blockIdx.x * 8 + wid;

    const float* src = (row < BATCH) ? (z_aug + (size_t)row * DIM)
                                     : (z_orig + (size_t)(row - BATCH) * DIM);
    float4 v0 = reinterpret_cast<const float4*>(src)[lid * 2];
    float4 v1 = reinterpret_cast<const float4*>(src)[lid * 2 + 1];

    float s = v0.x * v0.x + v0.y * v0.y + v0.z * v0.z + v0.w * v0.w
            + v1.x * v1.x + v1.y * v1.y + v1.z * v1.z + v1.w * v1.w;
    #pragma unroll
    for (int o = 16; o; o >>= 1) s += __shfl_xor_sync(0xffffffffu, s, o);

    float inv = 1.0f / fmaxf(sqrtf(s), 1e-8f);

    union { uint4 u; __nv_bfloat16 h[8]; } out;
    out.h[0] = __float2bfloat16(v0.x * inv);
    out.h[1] = __float2bfloat16(v0.y * inv);
    out.h[2] = __float2bfloat16(v0.z * inv);
    out.h[3] = __float2bfloat16(v0.w * inv);
    out.h[4] = __float2bfloat16(v1.x * inv);
    out.h[5] = __float2bfloat16(v1.y * inv);
    out.h[6] = __float2bfloat16(v1.z * inv);
    out.h[7] = __float2bfloat16(v1.w * inv);
    reinterpret_cast<uint4*>(g_zn + (size_t)row * DIM)[lid] = out.u;

    if (lid == 0) g_rowsum[row] = 0.0f;   // fused zero-init
}

// ============================================================================
// Kernel 2: upper-tri 128x128 tile GEMM (bf16 mma.sync), 4 warps x 64x64,
//           K-chunked 3-stage pipeline, exp epilogue, row+col sums, positives
// ============================================================================
__global__ void __launch_bounds__(128, 2)
gemm_exp_kernel() {
    extern __shared__ char smem[];
    uint32_t smem_base = smem_to_u32(smem);
    float* srow = reinterpret_cast<float*>(smem + SMEM_R_OFF);
    float* scol = reinterpret_cast<float*>(smem + SMEM_C_OFF);

    int tid  = threadIdx.x;
    int wid  = tid >> 5;       // 0..3
    int lane = tid & 31;
    int gid  = lane >> 2;      // 0..7
    int tig  = lane & 3;       // 0..3
    int sub  = lane >> 3;      // 0..3
    int li   = lane & 7;       // 0..7

    // --- decode (it, jt) with jt >= it ---
    int t = blockIdx.x;
    int it = 0;
    {
        int rem = NTILE;
        while (t >= rem) { t -= rem; rem--; it++; }
    }
    int jt = it + t;
    bool diag = (it == jt);

    int wm = wid >> 1;         // 0..1 : warp rows wm*64 .. +64
    int wn = wid & 1;          // 0..1 : warp cols wn*64 .. +64

    const char* gz = reinterpret_cast<const char*>(g_zn);
    const char* gA = gz + (size_t)(it * MT) * DIM * 2;
    const char* gB = gz + (size_t)(jt * NT) * DIM * 2;

    // chunk loader: chunk c (K byte offset c*128) into stage s (128 threads)
    auto load_chunk = [&](int c, int s) {
        uint32_t sa = smem_base + (uint32_t)(s * STAGE_SZ);
        #pragma unroll
        for (int x = 0; x < 8; x++) {
            int v   = x * 128 + tid;        // 0..1023
            int row = v >> 3;               // 0..127
            int cv  = v & 7;                // 16B vector in 128B row
            uint32_t off = SWZ((uint32_t)(row * 128 + cv * 16));
            size_t gofs = (size_t)row * (DIM * 2) + c * 128 + cv * 16;
            cp_async16(sa + STAGE_A + off, gA + gofs);
            if (!diag) cp_async16(sa + STAGE_B + off, gB + gofs);
        }
        cp_async_commit();
    };

    // --- prologue: fill stages 0..2 ---
    load_chunk(0, 0);
    load_chunk(1, 1);
    load_chunk(2, 2);
    srow[tid] = 0.0f; scol[tid] = 0.0f;

    // --- fragment addresses (swizzled, per-lane constant XOR) ---
    int rowA = wm * 64 + (sub & 1) * 8 + li;
    int rowB = wn * 64 + (sub >> 1) * 8 + li;
    uint32_t xorA = (uint32_t)((rowA & 7) << 4);
    uint32_t xorB = (uint32_t)((rowB & 7) << 4);
    uint32_t baseA = (uint32_t)(rowA * 128) + STAGE_A;
    uint32_t baseB = (uint32_t)(rowB * 128) + (diag ? STAGE_A : STAGE_B);
    uint32_t colA[4], colB[4];
    #pragma unroll
    for (int kk = 0; kk < 4; kk++) {
        colA[kk] = ((uint32_t)((sub >> 1) * 16 + kk * 32)) ^ xorA;
        colB[kk] = ((uint32_t)((sub & 1) * 16 + kk * 32)) ^ xorB;
    }

    float acc[4][8][4];
    #pragma unroll
    for (int mf = 0; mf < 4; mf++)
        #pragma unroll
        for (int nf = 0; nf < 8; nf++)
            #pragma unroll
            for (int q = 0; q < 4; q++) acc[mf][nf][q] = 0.0f;

    // MMA over one resident chunk (4 k-steps of 16)
    auto mma_chunk = [&](int s) {
        uint32_t sa = smem_base + (uint32_t)(s * STAGE_SZ);
        #pragma unroll
        for (int kk = 0; kk < 4; kk++) {
            uint32_t a[4][4];
            #pragma unroll
            for (int mf = 0; mf < 4; mf++)
                ldmatrix_x4(a[mf][0], a[mf][1], a[mf][2], a[mf][3],
                            sa + baseA + (uint32_t)(mf * 16 * 128) + colA[kk]);
            uint32_t b[8][2];
            #pragma unroll
            for (int nfp = 0; nfp < 8; nfp += 2)
                ldmatrix_x4(b[nfp][0], b[nfp][1], b[nfp + 1][0], b[nfp + 1][1],
                            sa + baseB + (uint32_t)(nfp * 8 * 128) + colB[kk]);
            #pragma unroll
            for (int mf = 0; mf < 4; mf++)
                #pragma unroll
                for (int nf = 0; nf < 8; nf++)
                    mma16816(acc[mf][nf], a[mf][0], a[mf][1], a[mf][2], a[mf][3],
                             b[nf][0], b[nf][1]);
        }
    };

    // --- pipelined mainloop (4 chunks, 3 stages) ---
    cp_async_wait<2>(); __syncthreads();
    mma_chunk(0);
    __syncthreads();                 // everyone done reading stage 0
    load_chunk(3, 0);

    cp_async_wait<2>(); __syncthreads();
    mma_chunk(1);

    cp_async_wait<1>(); __syncthreads();
    mma_chunk(2);

    cp_async_wait<0>(); __syncthreads();
    mma_chunk(0);

    // --- positives: tiles with jt-it==32 hold S[i, i+BATCH] on local diag ---
    if (jt - it == 32) {
        int c0l = wn * 64 + tig * 2;
        #pragma unroll
        for (int mf = 0; mf < 4; mf++) {
            int lr0 = wm * 64 + mf * 16 + gid;
            int lr1 = lr0 + 8;
            #pragma unroll
            for (int nf = 0; nf < 8; nf++) {
                int lc = c0l + nf * 8;
                if (lc     == lr0) g_pos[it * 128 + lr0] = acc[mf][nf][0];
                if (lc + 1 == lr0) g_pos[it * 128 + lr0] = acc[mf][nf][1];
                if (lc     == lr1) g_pos[it * 128 + lr1] = acc[mf][nf][2];
                if (lc + 1 == lr1) g_pos[it * 128 + lr1] = acc[mf][nf][3];
            }
        }
    }

    // --- Epilogue: exp in place (mask main diagonal only on diag tiles) ---
    if (diag) {
        int r0l = wm * 64 + gid;
        int c0l = wn * 64 + tig * 2;
        #pragma unroll
        for (int mf = 0; mf < 4; mf++) {
            int lr0 = r0l + mf * 16, lr1 = lr0 + 8;
            #pragma unroll
            for (int nf = 0; nf < 8; nf++) {
                int lc = c0l + nf * 8;
                float e0 = __expf(acc[mf][nf][0] * INV_TAU);
                float e1 = __expf(acc[mf][nf][1] * INV_TAU);
                float e2 = __expf(acc[mf][nf][2] * INV_TAU);
                float e3 = __expf(acc[mf][nf][3] * INV_TAU);
                if (lc     == lr0) e0 = 0.0f;
                if (lc + 1 == lr0) e1 = 0.0f;
                if (lc     == lr1) e2 = 0.0f;
                if (lc + 1 == lr1) e3 = 0.0f;
                acc[mf][nf][0] = e0; acc[mf][nf][1] = e1;
                acc[mf][nf][2] = e2; acc[mf][nf][3] = e3;
            }
        }
    } else {
        #pragma unroll
        for (int mf = 0; mf < 4; mf++)
            #pragma unroll
            for (int nf = 0; nf < 8; nf++)
                #pragma unroll
                for (int q = 0; q < 4; q++)
                    acc[mf][nf][q] = __expf(acc[mf][nf][q] * INV_TAU);
    }

    // --- row sums: 8 per thread (mf x rowhalf), reduce over tig lanes ---
    {
        float rsum[8];
        #pragma unroll
        for (int q = 0; q < 8; q++) rsum[q] = 0.0f;
        #pragma unroll
        for (int mf = 0; mf < 4; mf++)
            #pragma unroll
            for (int nf = 0; nf < 8; nf++) {
                rsum[mf * 2 + 0] += acc[mf][nf][0] + acc[mf][nf][1];
                rsum[mf * 2 + 1] += acc[mf][nf][2] + acc[mf][nf][3];
            }
        #pragma unroll
        for (int q = 0; q < 8; q++) {
            rsum[q] += __shfl_xor_sync(0xffffffffu, rsum[q], 1);
            rsum[q] += __shfl_xor_sync(0xffffffffu, rsum[q], 2);
        }
        if (tig == 0) {
            int rb = wm * 64 + gid;
            #pragma unroll
            for (int mf = 0; mf < 4; mf++) {
                atomicAdd(&srow[rb + mf * 16],     rsum[mf * 2 + 0]);
                atomicAdd(&srow[rb + mf * 16 + 8], rsum[mf * 2 + 1]);
            }
        }
    }

    // --- col sums (off-diagonal tiles only): reduce over gid lanes ---
    if (!diag) {
        float csum[8][2];
        #pragma unroll
        for (int nf = 0; nf < 8; nf++) {
            csum[nf][0] = 0.0f; csum[nf][1] = 0.0f;
            #pragma unroll
            for (int mf = 0; mf < 4; mf++) {
                csum[nf][0] += acc[mf][nf][0] + acc[mf][nf][2];
                csum[nf][1] += acc[mf][nf][1] + acc[mf][nf][3];
            }
        }
        #pragma unroll
        for (int nf = 0; nf < 8; nf++)
            #pragma unroll
            for (int q = 0; q < 2; q++) {
                csum[nf][q] += __shfl_xor_sync(0xffffffffu, csum[nf][q], 4);
                csum[nf][q] += __shfl_xor_sync(0xffffffffu, csum[nf][q], 8);
                csum[nf][q] += __shfl_xor_sync(0xffffffffu, csum[nf][q], 16);
            }
        if (gid == 0) {
            #pragma unroll
            for (int nf = 0; nf < 8; nf++) {
                int cb = wn * 64 + nf * 8 + tig * 2;
                atomicAdd(&scol[cb],     csum[nf][0]);
                atomicAdd(&scol[cb + 1], csum[nf][1]);
            }
        }
    }

    __syncthreads();
    atomicAdd(&g_rowsum[it * MT + tid], srow[tid]);
    if (!diag) atomicAdd(&g_rowsum[jt * NT + tid], scol[tid]);
}

// ============================================================================
// Kernel 3: single block — loss = sum_i (-pos_i/tau + log(rowsum_i)) / NROWS
// ============================================================================
__global__ void __launch_bounds__(1024) loss_kernel(float* __restrict__ out) {
    __shared__ float wsum[32];
    int tid = threadIdx.x;

    float v = 0.0f;
    #pragma unroll
    for (int k = 0; k < 8; k++) {
        int i = k * 1024 + tid;
        float pos = g_pos[i & (BATCH - 1)];
        v += -INV_TAU * pos + logf(g_rowsum[i]);
    }
    #pragma unroll
    for (int o = 16; o; o >>= 1) v += __shfl_xor_sync(0xffffffffu, v, o);
    if ((tid & 31) == 0) wsum[tid >> 5] = v;
    __syncthreads();
    if (tid < 32) {
        float s = wsum[tid];
        #pragma unroll
        for (int o = 16; o; o >>= 1) s += __shfl_xor_sync(0xffffffffu, s, o);
        if (tid == 0) out[0] = s * (1.0f / (float)NROWS);
    }
}

// ============================================================================
// kernel_launch
// ============================================================================
extern "C" void kernel_launch(void* const* d_in, const int* in_sizes, int n_in,
                              void* d_out, int out_size) {
    (void)in_sizes; (void)n_in; (void)out_size;
    const float* z_orig = (const float*)d_in[0];
    const float* z_aug  = (const float*)d_in[1];
    float* out = (float*)d_out;

    normalize_kernel<<<1024, 256>>>(z_orig, z_aug);

    cudaFuncSetAttribute(gemm_exp_kernel,
                         cudaFuncAttributeMaxDynamicSharedMemorySize, SMEM_TOTAL);
    gemm_exp_kernel<<<N_CTAS, 128, SMEM_TOTAL>>>();

    loss_kernel<<<1, 1024>>>(out);
}

// round 12
// speedup vs baseline: 1.2290x; 1.2290x over previous
#include <cuda_runtime.h>
#include <cuda_bf16.h>
#include <cstdint>

// ============================================================================
// Problem constants
// ============================================================================
#define BATCH   4096
#define DIM     256
#define NROWS   8192          // 2*BATCH
#define INV_TAU 2.0f          // 1/0.5

// GEMM tiling: 128x128 output tile, K chunked by 64, upper-tri tiles only
#define MT      128
#define NT      128
#define NTILE   64            // 64x64 tile grid; jt >= it: 2080 CTAs
#define N_CTAS  (NTILE * (NTILE + 1) / 2)
#define NSTAGE  3

// ============================================================================
// Device-global scratch
// ============================================================================
__device__ __align__(16) __nv_bfloat16 g_zn[NROWS * DIM];  // normalized, bf16
__device__ float g_rowsum[NROWS];
__device__ float g_pos[BATCH];                             // S[i, i+BATCH]

// ============================================================================
// Helpers
// ============================================================================
__device__ __forceinline__ uint32_t smem_to_u32(const void* smem_ptr) {
    uint32_t addr;
    asm("{ .reg .u64 tmp; cvta.to.shared.u64 tmp, %1; cvt.u32.u64 %0, tmp; }"
        : "=r"(addr) : "l"(smem_ptr));
    return addr;
}

__device__ __forceinline__ void cp_async16(uint32_t smem_addr, const void* gptr) {
    asm volatile("cp.async.cg.shared.global [%0], [%1], 16;"
                 :: "r"(smem_addr), "l"(gptr) : "memory");
}
__device__ __forceinline__ void cp_async_commit() {
    asm volatile("cp.async.commit_group;" ::: "memory");
}
template <int N>
__device__ __forceinline__ void cp_async_wait() {
    asm volatile("cp.async.wait_group %0;" :: "n"(N) : "memory");
}

__device__ __forceinline__ void ldmatrix_x4(uint32_t& r0, uint32_t& r1,
                                            uint32_t& r2, uint32_t& r3,
                                            uint32_t addr) {
    asm volatile("ldmatrix.sync.aligned.m8n8.x4.shared.b16 {%0,%1,%2,%3}, [%4];"
                 : "=r"(r0), "=r"(r1), "=r"(r2), "=r"(r3) : "r"(addr));
}

// mma.sync m16n8k16 bf16 -> f32, row-major A, col-major B
__device__ __forceinline__ void mma16816(float* c,
                                         uint32_t a0, uint32_t a1, uint32_t a2, uint32_t a3,
                                         uint32_t b0, uint32_t b1) {
    asm volatile(
        "mma.sync.aligned.m16n8k16.row.col.f32.bf16.bf16.f32 "
        "{%0,%1,%2,%3}, {%4,%5,%6,%7}, {%8,%9}, {%0,%1,%2,%3};"
        : "+f"(c[0]), "+f"(c[1]), "+f"(c[2]), "+f"(c[3])
        : "r"(a0), "r"(a1), "r"(a2), "r"(a3), "r"(b0), "r"(b1));
}

// SW128-style swizzle for 128-byte rows
#define SWZ(off) ((off) ^ (((off) >> 3) & 0x70))

// ============================================================================
// SMEM layout (dynamic): NSTAGE stages of {A:128x128B, B:128x128B}
// ============================================================================
static constexpr int STAGE_A    = 0;
static constexpr int STAGE_B    = 16384;
static constexpr int STAGE_SZ   = 32768;
static constexpr int SMEM_R_OFF = NSTAGE * STAGE_SZ;            // 98304
static constexpr int SMEM_C_OFF = SMEM_R_OFF + 128 * 4;
static constexpr int SMEM_TOTAL = SMEM_C_OFF + 128 * 4;         // 99328

// ============================================================================
// Kernel 1: L2-normalize rows -> bf16 (also zero-inits g_rowsum and out)
// ============================================================================
__global__ void __launch_bounds__(256) normalize_kernel(
    const float* __restrict__ z_orig,
    const float* __restrict__ z_aug,
    float* __restrict__ out
) {
    int wid = threadIdx.x >> 5;
    int lid = threadIdx.x & 31;
    int row = blockIdx.x * 8 + wid;

    if (blockIdx.x == 0 && threadIdx.x == 0) out[0] = 0.0f;

    const float* src = (row < BATCH) ? (z_aug + (size_t)row * DIM)
                                     : (z_orig + (size_t)(row - BATCH) * DIM);
    float4 v0 = reinterpret_cast<const float4*>(src)[lid * 2];
    float4 v1 = reinterpret_cast<const float4*>(src)[lid * 2 + 1];

    float s = v0.x * v0.x + v0.y * v0.y + v0.z * v0.z + v0.w * v0.w
            + v1.x * v1.x + v1.y * v1.y + v1.z * v1.z + v1.w * v1.w;
    #pragma unroll
    for (int o = 16; o; o >>= 1) s += __shfl_xor_sync(0xffffffffu, s, o);

    float inv = 1.0f / fmaxf(sqrtf(s), 1e-8f);

    union { uint4 u; __nv_bfloat16 h[8]; } outv;
    outv.h[0] = __float2bfloat16(v0.x * inv);
    outv.h[1] = __float2bfloat16(v0.y * inv);
    outv.h[2] = __float2bfloat16(v0.z * inv);
    outv.h[3] = __float2bfloat16(v0.w * inv);
    outv.h[4] = __float2bfloat16(v1.x * inv);
    outv.h[5] = __float2bfloat16(v1.y * inv);
    outv.h[6] = __float2bfloat16(v1.z * inv);
    outv.h[7] = __float2bfloat16(v1.w * inv);
    reinterpret_cast<uint4*>(g_zn + (size_t)row * DIM)[lid] = outv.u;

    if (lid == 0) g_rowsum[row] = 0.0f;   // fused zero-init
}

// ============================================================================
// Kernel 2: upper-tri 128x128 tile GEMM (bf16 mma.sync), 8 warps x 32x64,
//           K-chunked 3-stage pipeline, exp epilogue, row+col sums, positives
//           (identical to the 62.0us round-10 kernel)
// ============================================================================
__global__ void __launch_bounds__(256, 2)
gemm_exp_kernel() {
    extern __shared__ char smem[];
    uint32_t smem_base = smem_to_u32(smem);
    float* srow = reinterpret_cast<float*>(smem + SMEM_R_OFF);
    float* scol = reinterpret_cast<float*>(smem + SMEM_C_OFF);

    int tid  = threadIdx.x;
    int wid  = tid >> 5;
    int lane = tid & 31;
    int gid  = lane >> 2;      // 0..7
    int tig  = lane & 3;       // 0..3
    int sub  = lane >> 3;      // 0..3
    int li   = lane & 7;       // 0..7

    // --- decode (it, jt) with jt >= it ---
    int t = blockIdx.x;
    int it = 0;
    {
        int rem = NTILE;
        while (t >= rem) { t -= rem; rem--; it++; }
    }
    int jt = it + t;
    bool diag = (it == jt);

    int wm = wid >> 1;         // 0..3 : warp rows wm*32 .. +32
    int wn = wid & 1;          // 0..1 : warp cols wn*64 .. +64

    const char* gz = reinterpret_cast<const char*>(g_zn);
    const char* gA = gz + (size_t)(it * MT) * DIM * 2;
    const char* gB = gz + (size_t)(jt * NT) * DIM * 2;

    // chunk loader: chunk c (K byte offset c*128) into stage s
    auto load_chunk = [&](int c, int s) {
        uint32_t sa = smem_base + (uint32_t)(s * STAGE_SZ);
        #pragma unroll
        for (int x = 0; x < 4; x++) {
            int v   = x * 256 + tid;        // 0..1023
            int row = v >> 3;               // 0..127
            int cv  = v & 7;                // 16B vector in 128B row
            uint32_t off = SWZ((uint32_t)(row * 128 + cv * 16));
            size_t gofs = (size_t)row * (DIM * 2) + c * 128 + cv * 16;
            cp_async16(sa + STAGE_A + off, gA + gofs);
            if (!diag) cp_async16(sa + STAGE_B + off, gB + gofs);
        }
        cp_async_commit();
    };

    // --- prologue: fill stages 0..2 ---
    load_chunk(0, 0);
    load_chunk(1, 1);
    load_chunk(2, 2);
    if (tid < 128) { srow[tid] = 0.0f; scol[tid] = 0.0f; }

    // --- fragment addresses (swizzled, per-lane constant XOR) ---
    int rowA = wm * 32 + (sub & 1) * 8 + li;
    int rowB = wn * 64 + (sub >> 1) * 8 + li;
    uint32_t xorA = (uint32_t)((rowA & 7) << 4);
    uint32_t xorB = (uint32_t)((rowB & 7) << 4);
    uint32_t baseA = (uint32_t)(rowA * 128) + STAGE_A;
    uint32_t baseB = (uint32_t)(rowB * 128) + (diag ? STAGE_A : STAGE_B);
    uint32_t colA[4], colB[4];
    #pragma unroll
    for (int kk = 0; kk < 4; kk++) {
        colA[kk] = ((uint32_t)((sub >> 1) * 16 + kk * 32)) ^ xorA;
        colB[kk] = ((uint32_t)((sub & 1) * 16 + kk * 32)) ^ xorB;
    }

    float acc[2][8][4];
    #pragma unroll
    for (int mf = 0; mf < 2; mf++)
        #pragma unroll
        for (int nf = 0; nf < 8; nf++)
            #pragma unroll
            for (int q = 0; q < 4; q++) acc[mf][nf][q] = 0.0f;

    // MMA over one resident chunk (4 k-steps of 16)
    auto mma_chunk = [&](int s) {
        uint32_t sa = smem_base + (uint32_t)(s * STAGE_SZ);
        #pragma unroll
        for (int kk = 0; kk < 4; kk++) {
            uint32_t a[2][4];
            #pragma unroll
            for (int mf = 0; mf < 2; mf++)
                ldmatrix_x4(a[mf][0], a[mf][1], a[mf][2], a[mf][3],
                            sa + baseA + (uint32_t)(mf * 16 * 128) + colA[kk]);
            uint32_t b[8][2];
            #pragma unroll
            for (int nfp = 0; nfp < 8; nfp += 2)
                ldmatrix_x4(b[nfp][0], b[nfp][1], b[nfp + 1][0], b[nfp + 1][1],
                            sa + baseB + (uint32_t)(nfp * 8 * 128) + colB[kk]);
            #pragma unroll
            for (int mf = 0; mf < 2; mf++)
                #pragma unroll
                for (int nf = 0; nf < 8; nf++)
                    mma16816(acc[mf][nf], a[mf][0], a[mf][1], a[mf][2], a[mf][3],
                             b[nf][0], b[nf][1]);
        }
    };

    // --- pipelined mainloop (4 chunks, 3 stages) ---
    cp_async_wait<2>(); __syncthreads();
    mma_chunk(0);
    __syncthreads();                 // everyone done reading stage 0
    load_chunk(3, 0);

    cp_async_wait<2>(); __syncthreads();
    mma_chunk(1);

    cp_async_wait<1>(); __syncthreads();
    mma_chunk(2);

    cp_async_wait<0>(); __syncthreads();
    mma_chunk(0);

    // --- positives: tiles with jt-it==32 hold S[i, i+BATCH] on local diag ---
    if (jt - it == 32) {
        int c0l = wn * 64 + tig * 2;
        #pragma unroll
        for (int mf = 0; mf < 2; mf++) {
            int lr0 = wm * 32 + mf * 16 + gid;
            int lr1 = lr0 + 8;
            #pragma unroll
            for (int nf = 0; nf < 8; nf++) {
                int lc = c0l + nf * 8;
                if (lc     == lr0) g_pos[it * 128 + lr0] = acc[mf][nf][0];
                if (lc + 1 == lr0) g_pos[it * 128 + lr0] = acc[mf][nf][1];
                if (lc     == lr1) g_pos[it * 128 + lr1] = acc[mf][nf][2];
                if (lc + 1 == lr1) g_pos[it * 128 + lr1] = acc[mf][nf][3];
            }
        }
    }

    // --- Epilogue: exp in place (mask main diagonal only on diag tiles) ---
    if (diag) {
        int r0l = wm * 32 + gid;
        int c0l = wn * 64 + tig * 2;
        #pragma unroll
        for (int mf = 0; mf < 2; mf++) {
            int lr0 = r0l + mf * 16, lr1 = lr0 + 8;
            #pragma unroll
            for (int nf = 0; nf < 8; nf++) {
                int lc = c0l + nf * 8;
                float e0 = __expf(acc[mf][nf][0] * INV_TAU);
                float e1 = __expf(acc[mf][nf][1] * INV_TAU);
                float e2 = __expf(acc[mf][nf][2] * INV_TAU);
                float e3 = __expf(acc[mf][nf][3] * INV_TAU);
                if (lc     == lr0) e0 = 0.0f;
                if (lc + 1 == lr0) e1 = 0.0f;
                if (lc     == lr1) e2 = 0.0f;
                if (lc + 1 == lr1) e3 = 0.0f;
                acc[mf][nf][0] = e0; acc[mf][nf][1] = e1;
                acc[mf][nf][2] = e2; acc[mf][nf][3] = e3;
            }
        }
    } else {
        #pragma unroll
        for (int mf = 0; mf < 2; mf++)
            #pragma unroll
            for (int nf = 0; nf < 8; nf++)
                #pragma unroll
                for (int q = 0; q < 4; q++)
                    acc[mf][nf][q] = __expf(acc[mf][nf][q] * INV_TAU);
    }

    // --- row sums ---
    {
        float rsum[4] = {0.f, 0.f, 0.f, 0.f};
        #pragma unroll
        for (int mf = 0; mf < 2; mf++)
            #pragma unroll
            for (int nf = 0; nf < 8; nf++) {
                rsum[mf * 2 + 0] += acc[mf][nf][0] + acc[mf][nf][1];
                rsum[mf * 2 + 1] += acc[mf][nf][2] + acc[mf][nf][3];
            }
        #pragma unroll
        for (int q = 0; q < 4; q++) {
            rsum[q] += __shfl_xor_sync(0xffffffffu, rsum[q], 1);
            rsum[q] += __shfl_xor_sync(0xffffffffu, rsum[q], 2);
        }
        if (tig == 0) {
            int rb = wm * 32 + gid;
            atomicAdd(&srow[rb],      rsum[0]);
            atomicAdd(&srow[rb + 8],  rsum[1]);
            atomicAdd(&srow[rb + 16], rsum[2]);
            atomicAdd(&srow[rb + 24], rsum[3]);
        }
    }

    // --- col sums (off-diagonal tiles only) ---
    if (!diag) {
        float csum[8][2];
        #pragma unroll
        for (int nf = 0; nf < 8; nf++) {
            csum[nf][0] = acc[0][nf][0] + acc[0][nf][2] + acc[1][nf][0] + acc[1][nf][2];
            csum[nf][1] = acc[0][nf][1] + acc[0][nf][3] + acc[1][nf][1] + acc[1][nf][3];
        }
        #pragma unroll
        for (int nf = 0; nf < 8; nf++)
            #pragma unroll
            for (int q = 0; q < 2; q++) {
                csum[nf][q] += __shfl_xor_sync(0xffffffffu, csum[nf][q], 4);
                csum[nf][q] += __shfl_xor_sync(0xffffffffu, csum[nf][q], 8);
                csum[nf][q] += __shfl_xor_sync(0xffffffffu, csum[nf][q], 16);
            }
        if (gid == 0) {
            #pragma unroll
            for (int nf = 0; nf < 8; nf++) {
                int cb = wn * 64 + nf * 8 + tig * 2;
                atomicAdd(&scol[cb],     csum[nf][0]);
                atomicAdd(&scol[cb + 1], csum[nf][1]);
            }
        }
    }

    __syncthreads();
    if (tid < 128) {
        atomicAdd(&g_rowsum[it * MT + tid], srow[tid]);
        if (!diag) atomicAdd(&g_rowsum[jt * NT + tid], scol[tid]);
    }
}

// ============================================================================
// Kernel 3: 8 blocks — loss = sum_i (-pos_i/tau + log(rowsum_i)) / NROWS
//           (out[0] zero-initialized by normalize_kernel)
// ============================================================================
__global__ void __launch_bounds__(1024) loss_kernel(float* __restrict__ out) {
    __shared__ float wsum[32];
    int tid = threadIdx.x;
    int i = blockIdx.x * 1024 + tid;

    float pos = g_pos[i & (BATCH - 1)];
    float v = -INV_TAU * pos + logf(g_rowsum[i]);

    #pragma unroll
    for (int o = 16; o; o >>= 1) v += __shfl_xor_sync(0xffffffffu, v, o);
    if ((tid & 31) == 0) wsum[tid >> 5] = v;
    __syncthreads();
    if (tid < 32) {
        float s = wsum[tid];
        #pragma unroll
        for (int o = 16; o; o >>= 1) s += __shfl_xor_sync(0xffffffffu, s, o);
        if (tid == 0) atomicAdd(out, s * (1.0f / (float)NROWS));
    }
}

// ============================================================================
// kernel_launch
// ============================================================================
extern "C" void kernel_launch(void* const* d_in, const int* in_sizes, int n_in,
                              void* d_out, int out_size) {
    (void)in_sizes; (void)n_in; (void)out_size;
    const float* z_orig = (const float*)d_in[0];
    const float* z_aug  = (const float*)d_in[1];
    float* out = (float*)d_out;

    normalize_kernel<<<1024, 256>>>(z_orig, z_aug, out);

    cudaFuncSetAttribute(gemm_exp_kernel,
                         cudaFuncAttributeMaxDynamicSharedMemorySize, SMEM_TOTAL);
    gemm_exp_kernel<<<N_CTAS, 256, SMEM_TOTAL>>>();

    loss_kernel<<<8, 1024>>>(out);
}

// round 13
// speedup vs baseline: 1.2356x; 1.0053x over previous
#include <cuda_runtime.h>
#include <cuda_bf16.h>
#include <cstdint>

// ============================================================================
// Problem constants
// ============================================================================
#define BATCH   4096
#define DIM     256
#define NROWS   8192          // 2*BATCH
#define INV_TAU 2.0f          // 1/0.5

// GEMM tiling: 128x128 output tile, K chunked by 64, upper-tri tiles only
#define MT      128
#define NT      128
#define NTILE   64            // 64x64 tile grid; jt >= it: 2080 CTAs
#define N_CTAS  (NTILE * (NTILE + 1) / 2)
#define N_OFFD  (N_CTAS - NTILE)      // 2016 off-diagonal tiles (launched first)
#define NSTAGE  3

// ============================================================================
// Device-global scratch
// ============================================================================
__device__ __align__(16) __nv_bfloat16 g_zn[NROWS * DIM];  // normalized, bf16
__device__ float g_rowsum[NROWS];
__device__ float g_pos[BATCH];                             // S[i, i+BATCH]

// ============================================================================
// Helpers
// ============================================================================
__device__ __forceinline__ uint32_t smem_to_u32(const void* smem_ptr) {
    uint32_t addr;
    asm("{ .reg .u64 tmp; cvta.to.shared.u64 tmp, %1; cvt.u32.u64 %0, tmp; }"
        : "=r"(addr) : "l"(smem_ptr));
    return addr;
}

__device__ __forceinline__ void cp_async16(uint32_t smem_addr, const void* gptr) {
    asm volatile("cp.async.cg.shared.global [%0], [%1], 16;"
                 :: "r"(smem_addr), "l"(gptr) : "memory");
}
__device__ __forceinline__ void cp_async_commit() {
    asm volatile("cp.async.commit_group;" ::: "memory");
}
template <int N>
__device__ __forceinline__ void cp_async_wait() {
    asm volatile("cp.async.wait_group %0;" :: "n"(N) : "memory");
}

__device__ __forceinline__ void ldmatrix_x4(uint32_t& r0, uint32_t& r1,
                                            uint32_t& r2, uint32_t& r3,
                                            uint32_t addr) {
    asm volatile("ldmatrix.sync.aligned.m8n8.x4.shared.b16 {%0,%1,%2,%3}, [%4];"
                 : "=r"(r0), "=r"(r1), "=r"(r2), "=r"(r3) : "r"(addr));
}

// mma.sync m16n8k16 bf16 -> f32, row-major A, col-major B
__device__ __forceinline__ void mma16816(float* c,
                                         uint32_t a0, uint32_t a1, uint32_t a2, uint32_t a3,
                                         uint32_t b0, uint32_t b1) {
    asm volatile(
        "mma.sync.aligned.m16n8k16.row.col.f32.bf16.bf16.f32 "
        "{%0,%1,%2,%3}, {%4,%5,%6,%7}, {%8,%9}, {%0,%1,%2,%3};"
        : "+f"(c[0]), "+f"(c[1]), "+f"(c[2]), "+f"(c[3])
        : "r"(a0), "r"(a1), "r"(a2), "r"(a3), "r"(b0), "r"(b1));
}

// SW128-style swizzle for 128-byte rows
#define SWZ(off) ((off) ^ (((off) >> 3) & 0x70))

// ============================================================================
// SMEM layout (dynamic): NSTAGE stages of {A:128x128B, B:128x128B}
// ============================================================================
static constexpr int STAGE_A    = 0;
static constexpr int STAGE_B    = 16384;
static constexpr int STAGE_SZ   = 32768;
static constexpr int SMEM_R_OFF = NSTAGE * STAGE_SZ;            // 98304
static constexpr int SMEM_C_OFF = SMEM_R_OFF + 128 * 4;
static constexpr int SMEM_TOTAL = SMEM_C_OFF + 128 * 4;         // 99328

// ============================================================================
// Kernel 1: L2-normalize rows -> bf16 (2 rows per warp, 4 concurrent loads,
//           also zero-inits g_rowsum and out)
// ============================================================================
__global__ void __launch_bounds__(256) normalize_kernel(
    const float* __restrict__ z_orig,
    const float* __restrict__ z_aug,
    float* __restrict__ out
) {
    int wid = threadIdx.x >> 5;
    int lid = threadIdx.x & 31;
    int row0 = blockIdx.x * 16 + wid * 2;   // 512 blocks * 16 rows

    if (blockIdx.x == 0 && threadIdx.x == 0) out[0] = 0.0f;

    const float* src0 = (row0 < BATCH) ? (z_aug + (size_t)row0 * DIM)
                                       : (z_orig + (size_t)(row0 - BATCH) * DIM);
    int row1 = row0 + 1;
    const float* src1 = (row1 < BATCH) ? (z_aug + (size_t)row1 * DIM)
                                       : (z_orig + (size_t)(row1 - BATCH) * DIM);

    // issue all 4 loads up-front (MLP=4)
    float4 a0 = reinterpret_cast<const float4*>(src0)[lid * 2];
    float4 a1 = reinterpret_cast<const float4*>(src0)[lid * 2 + 1];
    float4 b0 = reinterpret_cast<const float4*>(src1)[lid * 2];
    float4 b1 = reinterpret_cast<const float4*>(src1)[lid * 2 + 1];

    float sa = a0.x * a0.x + a0.y * a0.y + a0.z * a0.z + a0.w * a0.w
             + a1.x * a1.x + a1.y * a1.y + a1.z * a1.z + a1.w * a1.w;
    float sb = b0.x * b0.x + b0.y * b0.y + b0.z * b0.z + b0.w * b0.w
             + b1.x * b1.x + b1.y * b1.y + b1.z * b1.z + b1.w * b1.w;
    #pragma unroll
    for (int o = 16; o; o >>= 1) {
        sa += __shfl_xor_sync(0xffffffffu, sa, o);
        sb += __shfl_xor_sync(0xffffffffu, sb, o);
    }

    float inva = 1.0f / fmaxf(sqrtf(sa), 1e-8f);
    float invb = 1.0f / fmaxf(sqrtf(sb), 1e-8f);

    union { uint4 u; __nv_bfloat16 h[8]; } oa, ob;
    oa.h[0] = __float2bfloat16(a0.x * inva);
    oa.h[1] = __float2bfloat16(a0.y * inva);
    oa.h[2] = __float2bfloat16(a0.z * inva);
    oa.h[3] = __float2bfloat16(a0.w * inva);
    oa.h[4] = __float2bfloat16(a1.x * inva);
    oa.h[5] = __float2bfloat16(a1.y * inva);
    oa.h[6] = __float2bfloat16(a1.z * inva);
    oa.h[7] = __float2bfloat16(a1.w * inva);
    ob.h[0] = __float2bfloat16(b0.x * invb);
    ob.h[1] = __float2bfloat16(b0.y * invb);
    ob.h[2] = __float2bfloat16(b0.z * invb);
    ob.h[3] = __float2bfloat16(b0.w * invb);
    ob.h[4] = __float2bfloat16(b1.x * invb);
    ob.h[5] = __float2bfloat16(b1.y * invb);
    ob.h[6] = __float2bfloat16(b1.z * invb);
    ob.h[7] = __float2bfloat16(b1.w * invb);
    reinterpret_cast<uint4*>(g_zn + (size_t)row0 * DIM)[lid] = oa.u;
    reinterpret_cast<uint4*>(g_zn + (size_t)row1 * DIM)[lid] = ob.u;

    if (lid == 0) { g_rowsum[row0] = 0.0f; g_rowsum[row1] = 0.0f; }
}

// ============================================================================
// Kernel 2: upper-tri 128x128 tile GEMM (bf16 mma.sync), 8 warps x 32x64,
//           3-stage pipeline, exp epilogue, row+col sums, positives.
//           Off-diagonal tiles launch first; cheap diagonal tiles form the tail.
// ============================================================================
__global__ void __launch_bounds__(256, 2)
gemm_exp_kernel() {
    extern __shared__ char smem[];
    uint32_t smem_base = smem_to_u32(smem);
    float* srow = reinterpret_cast<float*>(smem + SMEM_R_OFF);
    float* scol = reinterpret_cast<float*>(smem + SMEM_C_OFF);

    int tid  = threadIdx.x;
    int wid  = tid >> 5;
    int lane = tid & 31;
    int gid  = lane >> 2;      // 0..7
    int tig  = lane & 3;       // 0..3
    int sub  = lane >> 3;      // 0..3
    int li   = lane & 7;       // 0..7

    // --- decode tile: off-diag tiles first (t < N_OFFD), then diag tiles ---
    int it, jt;
    {
        int t = blockIdx.x;
        if (t < N_OFFD) {
            it = 0;
            int rem = NTILE - 1;          // # of jt > it for it=0
            while (t >= rem) { t -= rem; rem--; it++; }
            jt = it + 1 + t;
        } else {
            it = t - N_OFFD;
            jt = it;
        }
    }
    bool diag = (it == jt);

    int wm = wid >> 1;         // 0..3 : warp rows wm*32 .. +32
    int wn = wid & 1;          // 0..1 : warp cols wn*64 .. +64

    const char* gz = reinterpret_cast<const char*>(g_zn);
    const char* gA = gz + (size_t)(it * MT) * DIM * 2;
    const char* gB = gz + (size_t)(jt * NT) * DIM * 2;

    // chunk loader: chunk c (K byte offset c*128) into stage s
    auto load_chunk = [&](int c, int s) {
        uint32_t sa = smem_base + (uint32_t)(s * STAGE_SZ);
        #pragma unroll
        for (int x = 0; x < 4; x++) {
            int v   = x * 256 + tid;        // 0..1023
            int row = v >> 3;               // 0..127
            int cv  = v & 7;                // 16B vector in 128B row
            uint32_t off = SWZ((uint32_t)(row * 128 + cv * 16));
            size_t gofs = (size_t)row * (DIM * 2) + c * 128 + cv * 16;
            cp_async16(sa + STAGE_A + off, gA + gofs);
            if (!diag) cp_async16(sa + STAGE_B + off, gB + gofs);
        }
        cp_async_commit();
    };

    // --- prologue: fill stages 0..2 ---
    load_chunk(0, 0);
    load_chunk(1, 1);
    load_chunk(2, 2);
    if (tid < 128) { srow[tid] = 0.0f; scol[tid] = 0.0f; }

    // --- fragment addresses (swizzled, per-lane constant XOR) ---
    int rowA = wm * 32 + (sub & 1) * 8 + li;
    int rowB = wn * 64 + (sub >> 1) * 8 + li;
    uint32_t xorA = (uint32_t)((rowA & 7) << 4);
    uint32_t xorB = (uint32_t)((rowB & 7) << 4);
    uint32_t baseA = (uint32_t)(rowA * 128) + STAGE_A;
    uint32_t baseB = (uint32_t)(rowB * 128) + (diag ? STAGE_A : STAGE_B);
    uint32_t colA[4], colB[4];
    #pragma unroll
    for (int kk = 0; kk < 4; kk++) {
        colA[kk] = ((uint32_t)((sub >> 1) * 16 + kk * 32)) ^ xorA;
        colB[kk] = ((uint32_t)((sub & 1) * 16 + kk * 32)) ^ xorB;
    }

    float acc[2][8][4];
    #pragma unroll
    for (int mf = 0; mf < 2; mf++)
        #pragma unroll
        for (int nf = 0; nf < 8; nf++)
            #pragma unroll
            for (int q = 0; q < 4; q++) acc[mf][nf][q] = 0.0f;

    // MMA over one resident chunk (4 k-steps of 16)
    auto mma_chunk = [&](int s) {
        uint32_t sa = smem_base + (uint32_t)(s * STAGE_SZ);
        #pragma unroll
        for (int kk = 0; kk < 4; kk++) {
            uint32_t a[2][4];
            #pragma unroll
            for (int mf = 0; mf < 2; mf++)
                ldmatrix_x4(a[mf][0], a[mf][1], a[mf][2], a[mf][3],
                            sa + baseA + (uint32_t)(mf * 16 * 128) + colA[kk]);
            uint32_t b[8][2];
            #pragma unroll
            for (int nfp = 0; nfp < 8; nfp += 2)
                ldmatrix_x4(b[nfp][0], b[nfp][1], b[nfp + 1][0], b[nfp + 1][1],
                            sa + baseB + (uint32_t)(nfp * 8 * 128) + colB[kk]);
            #pragma unroll
            for (int mf = 0; mf < 2; mf++)
                #pragma unroll
                for (int nf = 0; nf < 8; nf++)
                    mma16816(acc[mf][nf], a[mf][0], a[mf][1], a[mf][2], a[mf][3],
                             b[nf][0], b[nf][1]);
        }
    };

    // --- pipelined mainloop (4 chunks, 3 stages) ---
    cp_async_wait<2>(); __syncthreads();
    mma_chunk(0);
    __syncthreads();                 // everyone done reading stage 0
    load_chunk(3, 0);

    cp_async_wait<2>(); __syncthreads();
    mma_chunk(1);

    cp_async_wait<1>(); __syncthreads();
    mma_chunk(2);

    cp_async_wait<0>(); __syncthreads();
    mma_chunk(0);

    // --- positives: tiles with jt-it==32 hold S[i, i+BATCH] on local diag ---
    if (jt - it == 32) {
        int c0l = wn * 64 + tig * 2;
        #pragma unroll
        for (int mf = 0; mf < 2; mf++) {
            int lr0 = wm * 32 + mf * 16 + gid;
            int lr1 = lr0 + 8;
            #pragma unroll
            for (int nf = 0; nf < 8; nf++) {
                int lc = c0l + nf * 8;
                if (lc     == lr0) g_pos[it * 128 + lr0] = acc[mf][nf][0];
                if (lc + 1 == lr0) g_pos[it * 128 + lr0] = acc[mf][nf][1];
                if (lc     == lr1) g_pos[it * 128 + lr1] = acc[mf][nf][2];
                if (lc + 1 == lr1) g_pos[it * 128 + lr1] = acc[mf][nf][3];
            }
        }
    }

    // --- Epilogue: exp in place (mask main diagonal only on diag tiles) ---
    if (diag) {
        int r0l = wm * 32 + gid;
        int c0l = wn * 64 + tig * 2;
        #pragma unroll
        for (int mf = 0; mf < 2; mf++) {
            int lr0 = r0l + mf * 16, lr1 = lr0 + 8;
            #pragma unroll
            for (int nf = 0; nf < 8; nf++) {
                int lc = c0l + nf * 8;
                float e0 = __expf(acc[mf][nf][0] * INV_TAU);
                float e1 = __expf(acc[mf][nf][1] * INV_TAU);
                float e2 = __expf(acc[mf][nf][2] * INV_TAU);
                float e3 = __expf(acc[mf][nf][3] * INV_TAU);
                if (lc     == lr0) e0 = 0.0f;
                if (lc + 1 == lr0) e1 = 0.0f;
                if (lc     == lr1) e2 = 0.0f;
                if (lc + 1 == lr1) e3 = 0.0f;
                acc[mf][nf][0] = e0; acc[mf][nf][1] = e1;
                acc[mf][nf][2] = e2; acc[mf][nf][3] = e3;
            }
        }
    } else {
        #pragma unroll
        for (int mf = 0; mf < 2; mf++)
            #pragma unroll
            for (int nf = 0; nf < 8; nf++)
                #pragma unroll
                for (int q = 0; q < 4; q++)
                    acc[mf][nf][q] = __expf(acc[mf][nf][q] * INV_TAU);
    }

    // --- row sums ---
    {
        float rsum[4] = {0.f, 0.f, 0.f, 0.f};
        #pragma unroll
        for (int mf = 0; mf < 2; mf++)
            #pragma unroll
            for (int nf = 0; nf < 8; nf++) {
                rsum[mf * 2 + 0] += acc[mf][nf][0] + acc[mf][nf][1];
                rsum[mf * 2 + 1] += acc[mf][nf][2] + acc[mf][nf][3];
            }
        #pragma unroll
        for (int q = 0; q < 4; q++) {
            rsum[q] += __shfl_xor_sync(0xffffffffu, rsum[q], 1);
            rsum[q] += __shfl_xor_sync(0xffffffffu, rsum[q], 2);
        }
        if (tig == 0) {
            int rb = wm * 32 + gid;
            atomicAdd(&srow[rb],      rsum[0]);
            atomicAdd(&srow[rb + 8],  rsum[1]);
            atomicAdd(&srow[rb + 16], rsum[2]);
            atomicAdd(&srow[rb + 24], rsum[3]);
        }
    }

    // --- col sums (off-diagonal tiles only) ---
    if (!diag) {
        float csum[8][2];
        #pragma unroll
        for (int nf = 0; nf < 8; nf++) {
            csum[nf][0] = acc[0][nf][0] + acc[0][nf][2] + acc[1][nf][0] + acc[1][nf][2];
            csum[nf][1] = acc[0][nf][1] + acc[0][nf][3] + acc[1][nf][1] + acc[1][nf][3];
        }
        #pragma unroll
        for (int nf = 0; nf < 8; nf++)
            #pragma unroll
            for (int q = 0; q < 2; q++) {
                csum[nf][q] += __shfl_xor_sync(0xffffffffu, csum[nf][q], 4);
                csum[nf][q] += __shfl_xor_sync(0xffffffffu, csum[nf][q], 8);
                csum[nf][q] += __shfl_xor_sync(0xffffffffu, csum[nf][q], 16);
            }
        if (gid == 0) {
            #pragma unroll
            for (int nf = 0; nf < 8; nf++) {
                int cb = wn * 64 + nf * 8 + tig * 2;
                atomicAdd(&scol[cb],     csum[nf][0]);
                atomicAdd(&scol[cb + 1], csum[nf][1]);
            }
        }
    }

    __syncthreads();
    if (tid < 128) {
        atomicAdd(&g_rowsum[it * MT + tid], srow[tid]);
        if (!diag) atomicAdd(&g_rowsum[jt * NT + tid], scol[tid]);
    }
}

// ============================================================================
// Kernel 3: 8 blocks — loss = sum_i (-pos_i/tau + log(rowsum_i)) / NROWS
// ============================================================================
__global__ void __launch_bounds__(1024) loss_kernel(float* __restrict__ out) {
    __shared__ float wsum[32];
    int tid = threadIdx.x;
    int i = blockIdx.x * 1024 + tid;

    float pos = g_pos[i & (BATCH - 1)];
    float v = -INV_TAU * pos + logf(g_rowsum[i]);

    #pragma unroll
    for (int o = 16; o; o >>= 1) v += __shfl_xor_sync(0xffffffffu, v, o);
    if ((tid & 31) == 0) wsum[tid >> 5] = v;
    __syncthreads();
    if (tid < 32) {
        float s = wsum[tid];
        #pragma unroll
        for (int o = 16; o; o >>= 1) s += __shfl_xor_sync(0xffffffffu, s, o);
        if (tid == 0) atomicAdd(out, s * (1.0f / (float)NROWS));
    }
}

// ============================================================================
// kernel_launch
// ============================================================================
extern "C" void kernel_launch(void* const* d_in, const int* in_sizes, int n_in,
                              void* d_out, int out_size) {
    (void)in_sizes; (void)n_in; (void)out_size;
    const float* z_orig = (const float*)d_in[0];
    const float* z_aug  = (const float*)d_in[1];
    float* out = (float*)d_out;

    normalize_kernel<<<512, 256>>>(z_orig, z_aug, out);

    cudaFuncSetAttribute(gemm_exp_kernel,
                         cudaFuncAttributeMaxDynamicSharedMemorySize, SMEM_TOTAL);
    gemm_exp_kernel<<<N_CTAS, 256, SMEM_TOTAL>>>();

    loss_kernel<<<8, 1024>>>(out);
}

// round 14
// speedup vs baseline: 1.2793x; 1.0354x over previous
#include <cuda_runtime.h>
#include <cuda_bf16.h>
#include <cstdint>

// ============================================================================
// Problem constants
// ============================================================================
#define BATCH   4096
#define DIM     256
#define NROWS   8192          // 2*BATCH
#define INV_TAU 2.0f          // 1/0.5
// exp(x/tau) = 2^(x * INV_TAU * log2(e))
#define EX2_SCALE 2.8853900817779268f

// GEMM tiling: 128x128 output tile, K chunked by 64, upper-tri tiles only
#define MT      128
#define NT      128
#define NTILE   64            // 64x64 tile grid; jt >= it: 2080 CTAs
#define N_CTAS  (NTILE * (NTILE + 1) / 2)
#define N_OFFD  (N_CTAS - NTILE)      // 2016 off-diagonal tiles (launched first)
#define NSTAGE  3

// ============================================================================
// Device-global scratch
// ============================================================================
__device__ __align__(16) __nv_bfloat16 g_zn[NROWS * DIM];  // normalized, bf16
__device__ float g_rowsum[NROWS];
__device__ float g_pos[BATCH];                             // S[i, i+BATCH]

// ============================================================================
// Helpers
// ============================================================================
__device__ __forceinline__ uint32_t smem_to_u32(const void* smem_ptr) {
    uint32_t addr;
    asm("{ .reg .u64 tmp; cvta.to.shared.u64 tmp, %1; cvt.u32.u64 %0, tmp; }"
        : "=r"(addr) : "l"(smem_ptr));
    return addr;
}

__device__ __forceinline__ void cp_async16(uint32_t smem_addr, const void* gptr) {
    asm volatile("cp.async.cg.shared.global [%0], [%1], 16;"
                 :: "r"(smem_addr), "l"(gptr) : "memory");
}
__device__ __forceinline__ void cp_async_commit() {
    asm volatile("cp.async.commit_group;" ::: "memory");
}
template <int N>
__device__ __forceinline__ void cp_async_wait() {
    asm volatile("cp.async.wait_group %0;" :: "n"(N) : "memory");
}

__device__ __forceinline__ void ldmatrix_x4(uint32_t& r0, uint32_t& r1,
                                            uint32_t& r2, uint32_t& r3,
                                            uint32_t addr) {
    asm volatile("ldmatrix.sync.aligned.m8n8.x4.shared.b16 {%0,%1,%2,%3}, [%4];"
                 : "=r"(r0), "=r"(r1), "=r"(r2), "=r"(r3) : "r"(addr));
}

// mma.sync m16n8k16 bf16 -> f32, row-major A, col-major B
__device__ __forceinline__ void mma16816(float* c,
                                         uint32_t a0, uint32_t a1, uint32_t a2, uint32_t a3,
                                         uint32_t b0, uint32_t b1) {
    asm volatile(
        "mma.sync.aligned.m16n8k16.row.col.f32.bf16.bf16.f32 "
        "{%0,%1,%2,%3}, {%4,%5,%6,%7}, {%8,%9}, {%0,%1,%2,%3};"
        : "+f"(c[0]), "+f"(c[1]), "+f"(c[2]), "+f"(c[3])
        : "r"(a0), "r"(a1), "r"(a2), "r"(a3), "r"(b0), "r"(b1));
}

// single-FMUL exp(x/tau): MUFU.EX2 on pre-scaled argument
__device__ __forceinline__ float exp_tau(float x) {
    float r;
    asm("ex2.approx.f32 %0, %1;" : "=f"(r) : "f"(x * EX2_SCALE));
    return r;
}

// SW128-style swizzle for 128-byte rows
#define SWZ(off) ((off) ^ (((off) >> 3) & 0x70))

// ============================================================================
// SMEM layout (dynamic): NSTAGE stages of {A:128x128B, B:128x128B}
// ============================================================================
static constexpr int STAGE_A    = 0;
static constexpr int STAGE_B    = 16384;
static constexpr int STAGE_SZ   = 32768;
static constexpr int SMEM_R_OFF = NSTAGE * STAGE_SZ;            // 98304
static constexpr int SMEM_C_OFF = SMEM_R_OFF + 128 * 4;
static constexpr int SMEM_TOTAL = SMEM_C_OFF + 128 * 4;         // 99328

// ============================================================================
// Kernel 1: L2-normalize rows -> bf16 (also zero-inits g_rowsum and out)
// ============================================================================
__global__ void __launch_bounds__(256) normalize_kernel(
    const float* __restrict__ z_orig,
    const float* __restrict__ z_aug,
    float* __restrict__ out
) {
    int wid = threadIdx.x >> 5;
    int lid = threadIdx.x & 31;
    int row = blockIdx.x * 8 + wid;

    if (blockIdx.x == 0 && threadIdx.x == 0) out[0] = 0.0f;

    const float* src = (row < BATCH) ? (z_aug + (size_t)row * DIM)
                                     : (z_orig + (size_t)(row - BATCH) * DIM);
    float4 v0 = reinterpret_cast<const float4*>(src)[lid * 2];
    float4 v1 = reinterpret_cast<const float4*>(src)[lid * 2 + 1];

    float s = v0.x * v0.x + v0.y * v0.y + v0.z * v0.z + v0.w * v0.w
            + v1.x * v1.x + v1.y * v1.y + v1.z * v1.z + v1.w * v1.w;
    #pragma unroll
    for (int o = 16; o; o >>= 1) s += __shfl_xor_sync(0xffffffffu, s, o);

    float inv = 1.0f / fmaxf(sqrtf(s), 1e-8f);

    union { uint4 u; __nv_bfloat16 h[8]; } outv;
    outv.h[0] = __float2bfloat16(v0.x * inv);
    outv.h[1] = __float2bfloat16(v0.y * inv);
    outv.h[2] = __float2bfloat16(v0.z * inv);
    outv.h[3] = __float2bfloat16(v0.w * inv);
    outv.h[4] = __float2bfloat16(v1.x * inv);
    outv.h[5] = __float2bfloat16(v1.y * inv);
    outv.h[6] = __float2bfloat16(v1.z * inv);
    outv.h[7] = __float2bfloat16(v1.w * inv);
    reinterpret_cast<uint4*>(g_zn + (size_t)row * DIM)[lid] = outv.u;

    if (lid == 0) g_rowsum[row] = 0.0f;   // fused zero-init
}

// ============================================================================
// Kernel 2: upper-tri 128x128 tile GEMM (bf16 mma.sync), 8 warps x 32x64,
//           3-stage pipeline, ex2 epilogue, row+col sums, positives.
//           Off-diagonal tiles launch first; cheap diagonal tiles form the tail.
// ============================================================================
__global__ void __launch_bounds__(256, 2)
gemm_exp_kernel() {
    extern __shared__ char smem[];
    uint32_t smem_base = smem_to_u32(smem);
    float* srow = reinterpret_cast<float*>(smem + SMEM_R_OFF);
    float* scol = reinterpret_cast<float*>(smem + SMEM_C_OFF);

    int tid  = threadIdx.x;
    int wid  = tid >> 5;
    int lane = tid & 31;
    int gid  = lane >> 2;      // 0..7
    int tig  = lane & 3;       // 0..3
    int sub  = lane >> 3;      // 0..3
    int li   = lane & 7;       // 0..7

    // --- decode tile: off-diag tiles first (t < N_OFFD), then diag tiles ---
    int it, jt;
    {
        int t = blockIdx.x;
        if (t < N_OFFD) {
            it = 0;
            int rem = NTILE - 1;
            while (t >= rem) { t -= rem; rem--; it++; }
            jt = it + 1 + t;
        } else {
            it = t - N_OFFD;
            jt = it;
        }
    }
    bool diag = (it == jt);

    int wm = wid >> 1;         // 0..3 : warp rows wm*32 .. +32
    int wn = wid & 1;          // 0..1 : warp cols wn*64 .. +64

    const char* gz = reinterpret_cast<const char*>(g_zn);
    const char* gA = gz + (size_t)(it * MT) * DIM * 2;
    const char* gB = gz + (size_t)(jt * NT) * DIM * 2;

    // chunk loader: chunk c (K byte offset c*128) into stage s
    auto load_chunk = [&](int c, int s) {
        uint32_t sa = smem_base + (uint32_t)(s * STAGE_SZ);
        #pragma unroll
        for (int x = 0; x < 4; x++) {
            int v   = x * 256 + tid;        // 0..1023
            int row = v >> 3;               // 0..127
            int cv  = v & 7;                // 16B vector in 128B row
            uint32_t off = SWZ((uint32_t)(row * 128 + cv * 16));
            size_t gofs = (size_t)row * (DIM * 2) + c * 128 + cv * 16;
            cp_async16(sa + STAGE_A + off, gA + gofs);
            if (!diag) cp_async16(sa + STAGE_B + off, gB + gofs);
        }
        cp_async_commit();
    };

    // --- prologue: fill stages 0..2 ---
    load_chunk(0, 0);
    load_chunk(1, 1);
    load_chunk(2, 2);
    if (tid < 128) { srow[tid] = 0.0f; scol[tid] = 0.0f; }

    // --- fragment addresses (swizzled, per-lane constant XOR) ---
    int rowA = wm * 32 + (sub & 1) * 8 + li;
    int rowB = wn * 64 + (sub >> 1) * 8 + li;
    uint32_t xorA = (uint32_t)((rowA & 7) << 4);
    uint32_t xorB = (uint32_t)((rowB & 7) << 4);
    uint32_t baseA = (uint32_t)(rowA * 128) + STAGE_A;
    uint32_t baseB = (uint32_t)(rowB * 128) + (diag ? STAGE_A : STAGE_B);
    uint32_t colA[4], colB[4];
    #pragma unroll
    for (int kk = 0; kk < 4; kk++) {
        colA[kk] = ((uint32_t)((sub >> 1) * 16 + kk * 32)) ^ xorA;
        colB[kk] = ((uint32_t)((sub & 1) * 16 + kk * 32)) ^ xorB;
    }

    float acc[2][8][4];
    #pragma unroll
    for (int mf = 0; mf < 2; mf++)
        #pragma unroll
        for (int nf = 0; nf < 8; nf++)
            #pragma unroll
            for (int q = 0; q < 4; q++) acc[mf][nf][q] = 0.0f;

    // MMA over one resident chunk (4 k-steps of 16)
    auto mma_chunk = [&](int s) {
        uint32_t sa = smem_base + (uint32_t)(s * STAGE_SZ);
        #pragma unroll
        for (int kk = 0; kk < 4; kk++) {
            uint32_t a[2][4];
            #pragma unroll
            for (int mf = 0; mf < 2; mf++)
                ldmatrix_x4(a[mf][0], a[mf][1], a[mf][2], a[mf][3],
                            sa + baseA + (uint32_t)(mf * 16 * 128) + colA[kk]);
            uint32_t b[8][2];
            #pragma unroll
            for (int nfp = 0; nfp < 8; nfp += 2)
                ldmatrix_x4(b[nfp][0], b[nfp][1], b[nfp + 1][0], b[nfp + 1][1],
                            sa + baseB + (uint32_t)(nfp * 8 * 128) + colB[kk]);
            #pragma unroll
            for (int mf = 0; mf < 2; mf++)
                #pragma unroll
                for (int nf = 0; nf < 8; nf++)
                    mma16816(acc[mf][nf], a[mf][0], a[mf][1], a[mf][2], a[mf][3],
                             b[nf][0], b[nf][1]);
        }
    };

    // --- pipelined mainloop (4 chunks, 3 stages) ---
    cp_async_wait<2>(); __syncthreads();
    mma_chunk(0);
    __syncthreads();                 // everyone done reading stage 0
    load_chunk(3, 0);

    cp_async_wait<2>(); __syncthreads();
    mma_chunk(1);

    cp_async_wait<1>(); __syncthreads();
    mma_chunk(2);

    cp_async_wait<0>(); __syncthreads();
    mma_chunk(0);

    // --- positives: tiles with jt-it==32 hold S[i, i+BATCH] on local diag ---
    if (jt - it == 32) {
        int c0l = wn * 64 + tig * 2;
        #pragma unroll
        for (int mf = 0; mf < 2; mf++) {
            int lr0 = wm * 32 + mf * 16 + gid;
            int lr1 = lr0 + 8;
            #pragma unroll
            for (int nf = 0; nf < 8; nf++) {
                int lc = c0l + nf * 8;
                if (lc     == lr0) g_pos[it * 128 + lr0] = acc[mf][nf][0];
                if (lc + 1 == lr0) g_pos[it * 128 + lr0] = acc[mf][nf][1];
                if (lc     == lr1) g_pos[it * 128 + lr1] = acc[mf][nf][2];
                if (lc + 1 == lr1) g_pos[it * 128 + lr1] = acc[mf][nf][3];
            }
        }
    }

    // --- Epilogue: ex2 in place (mask main diagonal only on diag tiles) ---
    if (diag) {
        int r0l = wm * 32 + gid;
        int c0l = wn * 64 + tig * 2;
        #pragma unroll
        for (int mf = 0; mf < 2; mf++) {
            int lr0 = r0l + mf * 16, lr1 = lr0 + 8;
            #pragma unroll
            for (int nf = 0; nf < 8; nf++) {
                int lc = c0l + nf * 8;
                float e0 = exp_tau(acc[mf][nf][0]);
                float e1 = exp_tau(acc[mf][nf][1]);
                float e2 = exp_tau(acc[mf][nf][2]);
                float e3 = exp_tau(acc[mf][nf][3]);
                if (lc     == lr0) e0 = 0.0f;
                if (lc + 1 == lr0) e1 = 0.0f;
                if (lc     == lr1) e2 = 0.0f;
                if (lc + 1 == lr1) e3 = 0.0f;
                acc[mf][nf][0] = e0; acc[mf][nf][1] = e1;
                acc[mf][nf][2] = e2; acc[mf][nf][3] = e3;
            }
        }
    } else {
        #pragma unroll
        for (int mf = 0; mf < 2; mf++)
            #pragma unroll
            for (int nf = 0; nf < 8; nf++)
                #pragma unroll
                for (int q = 0; q < 4; q++)
                    acc[mf][nf][q] = exp_tau(acc[mf][nf][q]);
    }

    // --- row sums ---
    {
        float rsum[4] = {0.f, 0.f, 0.f, 0.f};
        #pragma unroll
        for (int mf = 0; mf < 2; mf++)
            #pragma unroll
            for (int nf = 0; nf < 8; nf++) {
                rsum[mf * 2 + 0] += acc[mf][nf][0] + acc[mf][nf][1];
                rsum[mf * 2 + 1] += acc[mf][nf][2] + acc[mf][nf][3];
            }
        #pragma unroll
        for (int q = 0; q < 4; q++) {
            rsum[q] += __shfl_xor_sync(0xffffffffu, rsum[q], 1);
            rsum[q] += __shfl_xor_sync(0xffffffffu, rsum[q], 2);
        }
        if (tig == 0) {
            int rb = wm * 32 + gid;
            atomicAdd(&srow[rb],      rsum[0]);
            atomicAdd(&srow[rb + 8],  rsum[1]);
            atomicAdd(&srow[rb + 16], rsum[2]);
            atomicAdd(&srow[rb + 24], rsum[3]);
        }
    }

    // --- col sums (off-diagonal tiles only) ---
    if (!diag) {
        float csum[8][2];
        #pragma unroll
        for (int nf = 0; nf < 8; nf++) {
            csum[nf][0] = acc[0][nf][0] + acc[0][nf][2] + acc[1][nf][0] + acc[1][nf][2];
            csum[nf][1] = acc[0][nf][1] + acc[0][nf][3] + acc[1][nf][1] + acc[1][nf][3];
        }
        #pragma unroll
        for (int nf = 0; nf < 8; nf++)
            #pragma unroll
            for (int q = 0; q < 2; q++) {
                csum[nf][q] += __shfl_xor_sync(0xffffffffu, csum[nf][q], 4);
                csum[nf][q] += __shfl_xor_sync(0xffffffffu, csum[nf][q], 8);
                csum[nf][q] += __shfl_xor_sync(0xffffffffu, csum[nf][q], 16);
            }
        if (gid == 0) {
            #pragma unroll
            for (int nf = 0; nf < 8; nf++) {
                int cb = wn * 64 + nf * 8 + tig * 2;
                atomicAdd(&scol[cb],     csum[nf][0]);
                atomicAdd(&scol[cb + 1], csum[nf][1]);
            }
        }
    }

    __syncthreads();
    if (tid < 128) {
        atomicAdd(&g_rowsum[it * MT + tid], srow[tid]);
        if (!diag) atomicAdd(&g_rowsum[jt * NT + tid], scol[tid]);
    }
}

// ============================================================================
// Kernel 3: 8 blocks — loss = sum_i (-pos_i/tau + log(rowsum_i)) / NROWS
// ============================================================================
__global__ void __launch_bounds__(1024) loss_kernel(float* __restrict__ out) {
    __shared__ float wsum[32];
    int tid = threadIdx.x;
    int i = blockIdx.x * 1024 + tid;

    float pos = g_pos[i & (BATCH - 1)];
    float v = -INV_TAU * pos + logf(g_rowsum[i]);

    #pragma unroll
    for (int o = 16; o; o >>= 1) v += __shfl_xor_sync(0xffffffffu, v, o);
    if ((tid & 31) == 0) wsum[tid >> 5] = v;
    __syncthreads();
    if (tid < 32) {
        float s = wsum[tid];
        #pragma unroll
        for (int o = 16; o; o >>= 1) s += __shfl_xor_sync(0xffffffffu, s, o);
        if (tid == 0) atomicAdd(out, s * (1.0f / (float)NROWS));
    }
}

// ============================================================================
// kernel_launch
// ============================================================================
extern "C" void kernel_launch(void* const* d_in, const int* in_sizes, int n_in,
                              void* d_out, int out_size) {
    (void)in_sizes; (void)n_in; (void)out_size;
    const float* z_orig = (const float*)d_in[0];
    const float* z_aug  = (const float*)d_in[1];
    float* out = (float*)d_out;

    normalize_kernel<<<1024, 256>>>(z_orig, z_aug, out);

    cudaFuncSetAttribute(gemm_exp_kernel,
                         cudaFuncAttributeMaxDynamicSharedMemorySize, SMEM_TOTAL);
    gemm_exp_kernel<<<N_CTAS, 256, SMEM_TOTAL>>>();

    loss_kernel<<<8, 1024>>>(out);
}